// round 2
// baseline (speedup 1.0000x reference)
#include <cuda_runtime.h>
#include <math.h>

// Problem constants
#define BATCH 2
#define NTOK  2048
#define DMODEL 1024
#define NHEAD 16
#define DHEAD 64
#define HALFW 64          // window is |i-j| <= 64  (129 keys interior)

// Scratch (allocation-free rule: __device__ globals)
__device__ float g_qkv[(size_t)BATCH * NTOK * 3 * DMODEL];   // 50.3 MB
__device__ float g_att[(size_t)BATCH * NTOK * DMODEL];       // 16.8 MB

// ---------------------------------------------------------------------------
// SGEMM: C[M,N] = A[M,K] * B[K,N] + bias[N]   (all row-major, dims multiples
// of tile sizes: M=4096, N in {3072,1024}, K=1024)
// 128x128 block tile, BK=16, 256 threads, 8x8 per-thread micro-tile.
// ---------------------------------------------------------------------------
__global__ __launch_bounds__(256)
void sgemm_bias_kernel(const float* __restrict__ A, const float* __restrict__ Bm,
                       const float* __restrict__ bias, float* __restrict__ C,
                       int M, int N, int K)
{
    __shared__ float As[16][132];   // [k][m], padded to kill store conflicts
    __shared__ float Bs[16][128];   // [k][n]

    const int bx = blockIdx.x, by = blockIdx.y;
    const int tid = threadIdx.x;
    const int tx = tid & 15;        // 0..15  -> 8 cols each
    const int ty = tid >> 4;        // 0..15  -> 8 rows each

    const float* Ab = A + (size_t)by * 128 * K;
    const float* Bb = Bm + (size_t)bx * 128;

    const int aRow = tid >> 2;            // 0..63
    const int aCol = (tid & 3) << 2;      // 0,4,8,12
    const int bRow = tid >> 5;            // 0..7
    const int bCol = (tid & 31) << 2;     // 0..124

    float acc[8][8];
#pragma unroll
    for (int m = 0; m < 8; ++m)
#pragma unroll
        for (int n = 0; n < 8; ++n) acc[m][n] = 0.0f;

    for (int kt = 0; kt < K; kt += 16) {
#pragma unroll
        for (int i = 0; i < 2; ++i) {
            float4 a = *(const float4*)(Ab + (size_t)(aRow + i * 64) * K + kt + aCol);
            As[aCol + 0][aRow + i * 64] = a.x;
            As[aCol + 1][aRow + i * 64] = a.y;
            As[aCol + 2][aRow + i * 64] = a.z;
            As[aCol + 3][aRow + i * 64] = a.w;
        }
#pragma unroll
        for (int i = 0; i < 2; ++i) {
            *(float4*)&Bs[bRow + i * 8][bCol] =
                *(const float4*)(Bb + (size_t)(kt + bRow + i * 8) * N + bCol);
        }
        __syncthreads();

#pragma unroll
        for (int k = 0; k < 16; ++k) {
            float ra[8], rb[8];
            *(float4*)&ra[0] = *(const float4*)&As[k][ty * 8];
            *(float4*)&ra[4] = *(const float4*)&As[k][ty * 8 + 4];
            *(float4*)&rb[0] = *(const float4*)&Bs[k][tx * 8];
            *(float4*)&rb[4] = *(const float4*)&Bs[k][tx * 8 + 4];
#pragma unroll
            for (int m = 0; m < 8; ++m)
#pragma unroll
                for (int n = 0; n < 8; ++n)
                    acc[m][n] += ra[m] * rb[n];
        }
        __syncthreads();
    }

#pragma unroll
    for (int m = 0; m < 8; ++m) {
        size_t row = (size_t)by * 128 + ty * 8 + m;
        float* crow = C + row * N + (size_t)bx * 128;
#pragma unroll
        for (int n = 0; n < 8; ++n)
            crow[tx * 8 + n] = acc[m][n] + bias[(size_t)bx * 128 + tx * 8 + n];
    }
}

// ---------------------------------------------------------------------------
// Local windowed attention.
// One block = (query-tile of 64, head, batch). 256 threads = 8 warps,
// each warp owns 8 queries sequentially; lanes split window positions for
// scores and split head-dims for PV.
// K/V smem rows use stride 65 -> conflict-free lane-per-row access.
// ---------------------------------------------------------------------------
#define SK 65
#define ATTN_SMEM_FLOATS (64 * SK + 192 * SK + 192 * SK + 8 * 132)
#define ATTN_SMEM_BYTES  (ATTN_SMEM_FLOATS * 4)

__global__ __launch_bounds__(256)
void attn_kernel()
{
    extern __shared__ float sm[];
    float* Qs = sm;                 // [64][65]
    float* Ks = Qs + 64 * SK;       // [192][65]
    float* Vs = Ks + 192 * SK;      // [192][65]
    float* Sc = Vs + 192 * SK;      // [8][132] per-warp probs

    const int qt = blockIdx.x;      // 0..31
    const int h  = blockIdx.y;      // 0..15
    const int b  = blockIdx.z;      // 0..1
    const int i0 = qt * 64;
    const int jstart = max(0, i0 - HALFW);
    const int jend   = min(NTOK, i0 + 64 + HALFW);
    const int nrows  = jend - jstart;        // <= 192

    const int tid = threadIdx.x;
    const float* qkv = g_qkv;

    // Load Q tile
    for (int idx = tid; idx < 64 * 64; idx += 256) {
        int r = idx >> 6, d = idx & 63;
        Qs[r * SK + d] = qkv[(size_t)(b * NTOK + i0 + r) * (3 * DMODEL) + h * DHEAD + d];
    }
    // Load K/V window
    for (int idx = tid; idx < nrows * 64; idx += 256) {
        int r = idx >> 6, d = idx & 63;
        size_t base = (size_t)(b * NTOK + jstart + r) * (3 * DMODEL) + h * DHEAD + d;
        Ks[r * SK + d] = qkv[base + DMODEL];
        Vs[r * SK + d] = qkv[base + 2 * DMODEL];
    }
    __syncthreads();

    const int w = tid >> 5, lane = tid & 31;
    float* sc = Sc + w * 132;

    for (int qq = 0; qq < 8; ++qq) {
        const int ql = w * 8 + qq;
        const int i  = i0 + ql;
        const int jlo = max(0, i - HALFW);
        const int jhi = min(NTOK, i + HALFW + 1);
        const int nj  = jhi - jlo;           // 65..129
        const int rb  = jlo - jstart;

        // ---- scores: lane handles t = lane + 32*tt ----
        const float* kp[5];
#pragma unroll
        for (int tt = 0; tt < 5; ++tt) {
            int t = lane + 32 * tt;
            int rc = rb + min(t, nj - 1);    // clamp (invalid lanes masked later)
            kp[tt] = Ks + rc * SK;
        }
        float s[5] = {0.f, 0.f, 0.f, 0.f, 0.f};
        const float* qrow = Qs + ql * SK;
#pragma unroll 4
        for (int d = 0; d < 64; ++d) {
            float qd = qrow[d];
#pragma unroll
            for (int tt = 0; tt < 5; ++tt)
                s[tt] += qd * kp[tt][d];
        }
#pragma unroll
        for (int tt = 0; tt < 5; ++tt) s[tt] *= 0.125f;   // DH^-0.5

        // ---- softmax ----
        float mx = -INFINITY;
#pragma unroll
        for (int tt = 0; tt < 5; ++tt)
            if (lane + 32 * tt < nj) mx = fmaxf(mx, s[tt]);
#pragma unroll
        for (int off = 16; off > 0; off >>= 1)
            mx = fmaxf(mx, __shfl_xor_sync(0xffffffffu, mx, off));

        float lsum = 0.0f;
#pragma unroll
        for (int tt = 0; tt < 5; ++tt) {
            int t = lane + 32 * tt;
            if (t < nj) {
                float e = __expf(s[tt] - mx);
                sc[t] = e;
                lsum += e;
            }
        }
#pragma unroll
        for (int off = 16; off > 0; off >>= 1)
            lsum += __shfl_xor_sync(0xffffffffu, lsum, off);
        const float inv = 1.0f / lsum;
        __syncwarp();

        // ---- PV: lane owns dims lane and lane+32 ----
        float acc0 = 0.0f, acc1 = 0.0f;
        const float* vp = Vs + rb * SK;
#pragma unroll 4
        for (int t = 0; t < nj; ++t) {
            float p = sc[t];
            acc0 += p * vp[t * SK + lane];
            acc1 += p * vp[t * SK + 32 + lane];
        }
        size_t obase = (size_t)(b * NTOK + i) * DMODEL + h * DHEAD;
        g_att[obase + lane]      = acc0 * inv;
        g_att[obase + 32 + lane] = acc1 * inv;
        __syncwarp();   // protect sc before next query reuses it
    }
}

// ---------------------------------------------------------------------------
extern "C" void kernel_launch(void* const* d_in, const int* in_sizes, int n_in,
                              void* d_out, int out_size)
{
    const float* x     = (const float*)d_in[0];
    const float* Wqkv  = (const float*)d_in[1];
    const float* bqkv  = (const float*)d_in[2];
    const float* Wout  = (const float*)d_in[3];
    const float* bout  = (const float*)d_in[4];
    float* out = (float*)d_out;

    float *qkv_ptr, *att_ptr;
    cudaGetSymbolAddress((void**)&qkv_ptr, g_qkv);
    cudaGetSymbolAddress((void**)&att_ptr, g_att);

    cudaFuncSetAttribute(attn_kernel, cudaFuncAttributeMaxDynamicSharedMemorySize,
                         ATTN_SMEM_BYTES);

    const int M = BATCH * NTOK;        // 4096

    // GEMM1: qkv = x @ Wqkv + bqkv   [4096 x 3072]
    dim3 g1(3 * DMODEL / 128, M / 128);
    sgemm_bias_kernel<<<g1, 256>>>(x, Wqkv, bqkv, qkv_ptr, M, 3 * DMODEL, DMODEL);

    // Local attention -> g_att
    dim3 ga(NTOK / 64, NHEAD, BATCH);
    attn_kernel<<<ga, 256, ATTN_SMEM_BYTES>>>();

    // GEMM2: out = att @ Wout + bout  [4096 x 1024]
    dim3 g2(DMODEL / 128, M / 128);
    sgemm_bias_kernel<<<g2, 256>>>(att_ptr, Wout, bout, out, M, DMODEL, DMODEL);
}

// round 7
// speedup vs baseline: 1.7850x; 1.7850x over previous
#include <cuda_runtime.h>
#include <cuda_bf16.h>
#include <math.h>
#include <stdint.h>

// Problem constants
#define BATCH 2
#define NTOK  2048
#define DMODEL 1024
#define NHEAD 16
#define DHEAD 64
#define HALFW 64          // window is |i-j| <= 64  (129 keys interior)

// Scratch (allocation-free rule: __device__ globals)
__device__ float g_qkv[(size_t)BATCH * NTOK * 3 * DMODEL];   // 50.3 MB
__device__ float g_att[(size_t)BATCH * NTOK * DMODEL];       // 16.8 MB

// ============================================================================
// MMA helpers (sm_80-era ISA: valid on plain sm_103 target — NO tcgen05)
// ============================================================================
__device__ __forceinline__ uint32_t smem_to_u32(const void* smem_ptr) {
    uint32_t addr;
    asm("{ .reg .u64 tmp; cvta.to.shared.u64 tmp, %1; cvt.u32.u64 %0, tmp; }"
        : "=r"(addr) : "l"(smem_ptr));
    return addr;
}

__device__ __forceinline__ void ldsm_x4(uint32_t* r, uint32_t addr) {
    asm volatile("ldmatrix.sync.aligned.m8n8.x4.shared.b16 {%0,%1,%2,%3}, [%4];"
                 : "=r"(r[0]), "=r"(r[1]), "=r"(r[2]), "=r"(r[3]) : "r"(addr));
}
__device__ __forceinline__ void ldsm_x4_t(uint32_t* r, uint32_t addr) {
    asm volatile("ldmatrix.sync.aligned.m8n8.x4.trans.shared.b16 {%0,%1,%2,%3}, [%4];"
                 : "=r"(r[0]), "=r"(r[1]), "=r"(r[2]), "=r"(r[3]) : "r"(addr));
}
__device__ __forceinline__ void mma_bf16(float* c, const uint32_t* a, const uint32_t* b) {
    asm volatile(
        "mma.sync.aligned.m16n8k16.row.col.f32.bf16.bf16.f32 "
        "{%0,%1,%2,%3}, {%4,%5,%6,%7}, {%8,%9}, {%0,%1,%2,%3};"
        : "+f"(c[0]), "+f"(c[1]), "+f"(c[2]), "+f"(c[3])
        : "r"(a[0]), "r"(a[1]), "r"(a[2]), "r"(a[3]), "r"(b[0]), "r"(b[1]));
}
// pack {hi half = b, lo half = a} as bf16x2 (PTX: first src -> high half)
__device__ __forceinline__ uint32_t cvt2_bf16(float lo_v, float hi_v) {
    uint32_t r;
    asm("cvt.rn.bf16x2.f32 %0, %1, %2;" : "=r"(r) : "f"(hi_v), "f"(lo_v));
    return r;
}

// ============================================================================
// HMMA GEMM with bf16 2-term split:  C = A*B + bias
// A [M,K] row-major fp32, B [K,N] row-major fp32 (M,N,K multiples of tiles).
// CTA tile 128x128, BK=32, 256 threads (8 warps as 4m x 2n, warp tile 32x64).
// Smem: Ah/Al [128][40 bf16] (80B rows), Bh/Bl [32][136 bf16] (272B rows).
// Both strides conflict-free for ldmatrix (verified bank math).
// ============================================================================
#define SM_AH 0
#define SM_AL 10240
#define SM_BH 20480
#define SM_BL 29184
#define GEMM_SMEM_TOTAL 37888

__global__ __launch_bounds__(256, 1)
void tc_gemm_bias(const float* __restrict__ A, const float* __restrict__ Bm,
                  const float* __restrict__ bias, float* __restrict__ C,
                  int M, int N, int K)
{
    extern __shared__ char smem[];
    const uint32_t smem_base = smem_to_u32(smem);
    const int tid = threadIdx.x;
    const int lane = tid & 31;
    const int wid = tid >> 5;
    const int warp_m = wid & 3;       // 0..3 -> m rows [warp_m*32, +32)
    const int warp_n = wid >> 2;      // 0..1 -> n cols [warp_n*64, +64)
    const int bx = blockIdx.x, by = blockIdx.y;

    const float* Ab = A + (size_t)by * 128 * K;
    const float* Bb = Bm + (size_t)bx * 128;

    float acc[2][8][4];
#pragma unroll
    for (int mt = 0; mt < 2; ++mt)
#pragma unroll
        for (int nt = 0; nt < 8; ++nt)
#pragma unroll
            for (int e = 0; e < 4; ++e) acc[mt][nt][e] = 0.0f;

    // per-thread ldmatrix base addresses
    const uint32_t aAddrBase = smem_base + SM_AH
        + (uint32_t)(warp_m * 32 + (lane & 15)) * 80 + (uint32_t)(lane >> 4) * 16;
    const uint32_t bAddrBase = smem_base + SM_BH
        + (uint32_t)((lane & 7) + ((lane >> 3) & 1) * 8) * 272
        + (uint32_t)warp_n * 128 + (uint32_t)(lane >> 4) * 16;

    // global-load index precompute
    const int am = tid >> 3;          // + 32*j  (rows 0..127)
    const int ac4 = tid & 7;          // float4 col within 32-k chunk
    const int bk = tid >> 5;          // + 8*j   (k rows 0..31)
    const int bn4 = tid & 31;         // float4 col within 128-n

    float4 pa[4], pb[4];
    const int nchunks = K >> 5;       // K/32

    // prefetch chunk 0
#pragma unroll
    for (int j = 0; j < 4; ++j) {
        pa[j] = *(const float4*)(Ab + (size_t)(am + 32 * j) * K + ac4 * 4);
        pb[j] = *(const float4*)(Bb + (size_t)(bk + 8 * j) * N + bn4 * 4);
    }

    for (int c = 0; c < nchunks; ++c) {
        if (c) __syncthreads();       // previous compute done before smem overwrite

        // ---- convert + store to smem (Dekker bf16 split) ----
#pragma unroll
        for (int j = 0; j < 4; ++j) {
            float4 a = pa[j];
            uint32_t h01 = cvt2_bf16(a.x, a.y);
            uint32_t h23 = cvt2_bf16(a.z, a.w);
            float rx = a.x - __uint_as_float(h01 << 16);
            float ry = a.y - __uint_as_float(h01 & 0xFFFF0000u);
            float rz = a.z - __uint_as_float(h23 << 16);
            float rw = a.w - __uint_as_float(h23 & 0xFFFF0000u);
            uint32_t l01 = cvt2_bf16(rx, ry);
            uint32_t l23 = cvt2_bf16(rz, rw);
            uint32_t off = (uint32_t)(am + 32 * j) * 80 + (uint32_t)ac4 * 8;
            *(uint2*)(smem + SM_AH + off) = make_uint2(h01, h23);
            *(uint2*)(smem + SM_AL + off) = make_uint2(l01, l23);
        }
#pragma unroll
        for (int j = 0; j < 4; ++j) {
            float4 b = pb[j];
            uint32_t h01 = cvt2_bf16(b.x, b.y);
            uint32_t h23 = cvt2_bf16(b.z, b.w);
            float rx = b.x - __uint_as_float(h01 << 16);
            float ry = b.y - __uint_as_float(h01 & 0xFFFF0000u);
            float rz = b.z - __uint_as_float(h23 << 16);
            float rw = b.w - __uint_as_float(h23 & 0xFFFF0000u);
            uint32_t l01 = cvt2_bf16(rx, ry);
            uint32_t l23 = cvt2_bf16(rz, rw);
            uint32_t off = (uint32_t)(bk + 8 * j) * 272 + (uint32_t)bn4 * 8;
            *(uint2*)(smem + SM_BH + off) = make_uint2(h01, h23);
            *(uint2*)(smem + SM_BL + off) = make_uint2(l01, l23);
        }
        __syncthreads();

        // ---- prefetch next chunk (overlaps with MMA below) ----
        if (c + 1 < nchunks) {
            const int kc = (c + 1) << 5;
#pragma unroll
            for (int j = 0; j < 4; ++j) {
                pa[j] = *(const float4*)(Ab + (size_t)(am + 32 * j) * K + kc + ac4 * 4);
                pb[j] = *(const float4*)(Bb + (size_t)(bk + kc + 8 * j) * N + bn4 * 4);
            }
        }

        // ---- compute: 2 k16 steps ----
#pragma unroll
        for (int ks = 0; ks < 2; ++ks) {
            uint32_t ah[2][4], al[2][4];
#pragma unroll
            for (int mt = 0; mt < 2; ++mt) {
                uint32_t addr = aAddrBase + (uint32_t)(mt * 16) * 80 + (uint32_t)ks * 32;
                ldsm_x4(ah[mt], addr);
                ldsm_x4(al[mt], addr + (SM_AL - SM_AH));
            }
            uint32_t bh[4][4], bl[4][4];
#pragma unroll
            for (int ng = 0; ng < 4; ++ng) {
                uint32_t addr = bAddrBase + (uint32_t)(ks * 16) * 272 + (uint32_t)ng * 32;
                ldsm_x4_t(bh[ng], addr);
                ldsm_x4_t(bl[ng], addr + (SM_BL - SM_BH));
            }
#pragma unroll
            for (int mt = 0; mt < 2; ++mt) {
#pragma unroll
                for (int ng = 0; ng < 4; ++ng) {
                    mma_bf16(acc[mt][2 * ng], ah[mt], bh[ng]);
                    mma_bf16(acc[mt][2 * ng], ah[mt], bl[ng]);
                    mma_bf16(acc[mt][2 * ng], al[mt], bh[ng]);
                    mma_bf16(acc[mt][2 * ng + 1], ah[mt], bh[ng] + 2);
                    mma_bf16(acc[mt][2 * ng + 1], ah[mt], bl[ng] + 2);
                    mma_bf16(acc[mt][2 * ng + 1], al[mt], bh[ng] + 2);
                }
            }
        }
    }

    // ---- epilogue: acc -> C with bias ----
    const int row0 = by * 128 + warp_m * 32 + (lane >> 2);
    const int col0 = bx * 128 + warp_n * 64 + (lane & 3) * 2;
#pragma unroll
    for (int mt = 0; mt < 2; ++mt) {
#pragma unroll
        for (int nt = 0; nt < 8; ++nt) {
            int r = row0 + mt * 16;
            int ccol = col0 + nt * 8;
            float b0 = bias[ccol], b1 = bias[ccol + 1];
            float2 v0 = make_float2(acc[mt][nt][0] + b0, acc[mt][nt][1] + b1);
            float2 v1 = make_float2(acc[mt][nt][2] + b0, acc[mt][nt][3] + b1);
            *(float2*)(C + (size_t)r * N + ccol) = v0;
            *(float2*)(C + (size_t)(r + 8) * N + ccol) = v1;
        }
    }
}

// ---------------------------------------------------------------------------
// Local windowed attention (unchanged — fp32, smem-resident window).
// ---------------------------------------------------------------------------
#define SK 65
#define ATTN_SMEM_FLOATS (64 * SK + 192 * SK + 192 * SK + 8 * 132)
#define ATTN_SMEM_BYTES  (ATTN_SMEM_FLOATS * 4)

__global__ __launch_bounds__(256)
void attn_kernel()
{
    extern __shared__ float sm[];
    float* Qs = sm;                 // [64][65]
    float* Ks = Qs + 64 * SK;       // [192][65]
    float* Vs = Ks + 192 * SK;      // [192][65]
    float* Sc = Vs + 192 * SK;      // [8][132] per-warp probs

    const int qt = blockIdx.x;      // 0..31
    const int h  = blockIdx.y;      // 0..15
    const int b  = blockIdx.z;      // 0..1
    const int i0 = qt * 64;
    const int jstart = max(0, i0 - HALFW);
    const int jend   = min(NTOK, i0 + 64 + HALFW);
    const int nrows  = jend - jstart;        // <= 192

    const int tid = threadIdx.x;
    const float* qkv = g_qkv;

    for (int idx = tid; idx < 64 * 64; idx += 256) {
        int r = idx >> 6, d = idx & 63;
        Qs[r * SK + d] = qkv[(size_t)(b * NTOK + i0 + r) * (3 * DMODEL) + h * DHEAD + d];
    }
    for (int idx = tid; idx < nrows * 64; idx += 256) {
        int r = idx >> 6, d = idx & 63;
        size_t base = (size_t)(b * NTOK + jstart + r) * (3 * DMODEL) + h * DHEAD + d;
        Ks[r * SK + d] = qkv[base + DMODEL];
        Vs[r * SK + d] = qkv[base + 2 * DMODEL];
    }
    __syncthreads();

    const int w = tid >> 5, lane = tid & 31;
    float* sc = Sc + w * 132;

    for (int qq = 0; qq < 8; ++qq) {
        const int ql = w * 8 + qq;
        const int i  = i0 + ql;
        const int jlo = max(0, i - HALFW);
        const int jhi = min(NTOK, i + HALFW + 1);
        const int nj  = jhi - jlo;           // 65..129
        const int rb  = jlo - jstart;

        const float* kp[5];
#pragma unroll
        for (int tt = 0; tt < 5; ++tt) {
            int t = lane + 32 * tt;
            int rc = rb + min(t, nj - 1);
            kp[tt] = Ks + rc * SK;
        }
        float s[5] = {0.f, 0.f, 0.f, 0.f, 0.f};
        const float* qrow = Qs + ql * SK;
#pragma unroll 4
        for (int d = 0; d < 64; ++d) {
            float qd = qrow[d];
#pragma unroll
            for (int tt = 0; tt < 5; ++tt)
                s[tt] += qd * kp[tt][d];
        }
#pragma unroll
        for (int tt = 0; tt < 5; ++tt) s[tt] *= 0.125f;

        float mx = -INFINITY;
#pragma unroll
        for (int tt = 0; tt < 5; ++tt)
            if (lane + 32 * tt < nj) mx = fmaxf(mx, s[tt]);
#pragma unroll
        for (int off = 16; off > 0; off >>= 1)
            mx = fmaxf(mx, __shfl_xor_sync(0xffffffffu, mx, off));

        float lsum = 0.0f;
#pragma unroll
        for (int tt = 0; tt < 5; ++tt) {
            int t = lane + 32 * tt;
            if (t < nj) {
                float e = __expf(s[tt] - mx);
                sc[t] = e;
                lsum += e;
            }
        }
#pragma unroll
        for (int off = 16; off > 0; off >>= 1)
            lsum += __shfl_xor_sync(0xffffffffu, lsum, off);
        const float inv = 1.0f / lsum;
        __syncwarp();

        float acc0 = 0.0f, acc1 = 0.0f;
        const float* vp = Vs + rb * SK;
#pragma unroll 4
        for (int t = 0; t < nj; ++t) {
            float p = sc[t];
            acc0 += p * vp[t * SK + lane];
            acc1 += p * vp[t * SK + 32 + lane];
        }
        size_t obase = (size_t)(b * NTOK + i) * DMODEL + h * DHEAD;
        g_att[obase + lane]      = acc0 * inv;
        g_att[obase + 32 + lane] = acc1 * inv;
        __syncwarp();
    }
}

// ---------------------------------------------------------------------------
extern "C" void kernel_launch(void* const* d_in, const int* in_sizes, int n_in,
                              void* d_out, int out_size)
{
    const float* x     = (const float*)d_in[0];
    const float* Wqkv  = (const float*)d_in[1];
    const float* bqkv  = (const float*)d_in[2];
    const float* Wout  = (const float*)d_in[3];
    const float* bout  = (const float*)d_in[4];
    float* out = (float*)d_out;

    float *qkv_ptr, *att_ptr;
    cudaGetSymbolAddress((void**)&qkv_ptr, g_qkv);
    cudaGetSymbolAddress((void**)&att_ptr, g_att);

    cudaFuncSetAttribute(tc_gemm_bias, cudaFuncAttributeMaxDynamicSharedMemorySize,
                         GEMM_SMEM_TOTAL);
    cudaFuncSetAttribute(attn_kernel, cudaFuncAttributeMaxDynamicSharedMemorySize,
                         ATTN_SMEM_BYTES);

    const int M = BATCH * NTOK;        // 4096

    // GEMM1: qkv = x @ Wqkv + bqkv   [4096 x 3072]
    dim3 g1(3 * DMODEL / 128, M / 128);
    tc_gemm_bias<<<g1, 256, GEMM_SMEM_TOTAL>>>(x, Wqkv, bqkv, qkv_ptr,
                                               M, 3 * DMODEL, DMODEL);

    // Local attention -> g_att
    dim3 ga(NTOK / 64, NHEAD, BATCH);
    attn_kernel<<<ga, 256, ATTN_SMEM_BYTES>>>();

    // GEMM2: out = att @ Wout + bout  [4096 x 1024]
    dim3 g2(DMODEL / 128, M / 128);
    tc_gemm_bias<<<g2, 256, GEMM_SMEM_TOTAL>>>(att_ptr, Wout, bout, out,
                                               M, DMODEL, DMODEL);
}

// round 12
// speedup vs baseline: 2.3878x; 1.3377x over previous
#include <cuda_runtime.h>
#include <cuda_bf16.h>
#include <math.h>
#include <stdint.h>

// Problem constants
#define BATCH 2
#define NTOK  2048
#define DMODEL 1024
#define NHEAD 16
#define DHEAD 64
#define HALFW 64          // window is |i-j| <= 64  (129 keys interior)

// Scratch (allocation-free rule: __device__ globals)
__device__ float g_qkv[(size_t)BATCH * NTOK * 3 * DMODEL];   // 50.3 MB
__device__ float g_att[(size_t)BATCH * NTOK * DMODEL];       // 16.8 MB

// ============================================================================
// MMA helpers (sm_80-era ISA: valid on plain sm_103 target — NO tcgen05)
// ============================================================================
__device__ __forceinline__ uint32_t smem_to_u32(const void* smem_ptr) {
    uint32_t addr;
    asm("{ .reg .u64 tmp; cvta.to.shared.u64 tmp, %1; cvt.u32.u64 %0, tmp; }"
        : "=r"(addr) : "l"(smem_ptr));
    return addr;
}

__device__ __forceinline__ void ldsm_x4(uint32_t* r, uint32_t addr) {
    asm volatile("ldmatrix.sync.aligned.m8n8.x4.shared.b16 {%0,%1,%2,%3}, [%4];"
                 : "=r"(r[0]), "=r"(r[1]), "=r"(r[2]), "=r"(r[3]) : "r"(addr));
}
__device__ __forceinline__ void ldsm_x4_t(uint32_t* r, uint32_t addr) {
    asm volatile("ldmatrix.sync.aligned.m8n8.x4.trans.shared.b16 {%0,%1,%2,%3}, [%4];"
                 : "=r"(r[0]), "=r"(r[1]), "=r"(r[2]), "=r"(r[3]) : "r"(addr));
}
// mma with explicit B register pair (lets callers pick {b0,b1} or {b0,b2} pairings)
__device__ __forceinline__ void mma2(float* c, const uint32_t* a, uint32_t b0, uint32_t b1) {
    asm volatile(
        "mma.sync.aligned.m16n8k16.row.col.f32.bf16.bf16.f32 "
        "{%0,%1,%2,%3}, {%4,%5,%6,%7}, {%8,%9}, {%0,%1,%2,%3};"
        : "+f"(c[0]), "+f"(c[1]), "+f"(c[2]), "+f"(c[3])
        : "r"(a[0]), "r"(a[1]), "r"(a[2]), "r"(a[3]), "r"(b0), "r"(b1));
}
// pack: lo_v -> low 16 bits, hi_v -> high 16 bits
__device__ __forceinline__ uint32_t cvt2_bf16(float lo_v, float hi_v) {
    uint32_t r;
    asm("cvt.rn.bf16x2.f32 %0, %1, %2;" : "=r"(r) : "f"(hi_v), "f"(lo_v));
    return r;
}

// Dekker split of a float4 into bf16 hi/lo planes; 8B store to each plane.
__device__ __forceinline__ void split_store8(char* dstH, char* dstL, float4 v, uint32_t off) {
    uint32_t h01 = cvt2_bf16(v.x, v.y);
    uint32_t h23 = cvt2_bf16(v.z, v.w);
    float rx = v.x - __uint_as_float(h01 << 16);
    float ry = v.y - __uint_as_float(h01 & 0xFFFF0000u);
    float rz = v.z - __uint_as_float(h23 << 16);
    float rw = v.w - __uint_as_float(h23 & 0xFFFF0000u);
    uint32_t l01 = cvt2_bf16(rx, ry);
    uint32_t l23 = cvt2_bf16(rz, rw);
    *(uint2*)(dstH + off) = make_uint2(h01, h23);
    *(uint2*)(dstL + off) = make_uint2(l01, l23);
}

// ============================================================================
// HMMA GEMM with bf16 2-term split:  C = A*B + bias
// CTA tile 128x128, BK=32, 256 threads (8 warps 4m x 2n, warp tile 32x64).
// PING-PONG smem buffers: STS of chunk c+1 interleaves with MMAs of chunk c.
// Per buffer: Ah/Al [128][40 bf16] (80B rows), Bh/Bl [32][136 bf16] (272B rows).
// ============================================================================
#define SM_AH 0
#define SM_AL 10240
#define SM_BH 20480
#define SM_BL 29184
#define GB    37888                  // bytes per buffer
#define GEMM_SMEM_TOTAL (2 * GB)

__global__ __launch_bounds__(256, 1)
void tc_gemm_bias(const float* __restrict__ A, const float* __restrict__ Bm,
                  const float* __restrict__ bias, float* __restrict__ C,
                  int M, int N, int K)
{
    extern __shared__ char smem[];
    const uint32_t smem_base = smem_to_u32(smem);
    const int tid = threadIdx.x;
    const int lane = tid & 31;
    const int wid = tid >> 5;
    const int warp_m = wid & 3;
    const int warp_n = wid >> 2;
    const int bx = blockIdx.x, by = blockIdx.y;

    const float* Ab = A + (size_t)by * 128 * K;
    const float* Bb = Bm + (size_t)bx * 128;

    float acc[2][8][4];
#pragma unroll
    for (int mt = 0; mt < 2; ++mt)
#pragma unroll
        for (int nt = 0; nt < 8; ++nt)
#pragma unroll
            for (int e = 0; e < 4; ++e) acc[mt][nt][e] = 0.0f;

    const uint32_t aAddrBase = smem_base + SM_AH
        + (uint32_t)(warp_m * 32 + (lane & 15)) * 80 + (uint32_t)(lane >> 4) * 16;
    const uint32_t bAddrBase = smem_base + SM_BH
        + (uint32_t)(lane & 15) * 272
        + (uint32_t)warp_n * 128 + (uint32_t)(lane >> 4) * 16;

    const int am = tid >> 3;          // A row (+32j)
    const int ac4 = tid & 7;          // A float4 col in 32-k chunk
    const int bk = tid >> 5;          // B k row (+8j)
    const int bn4 = tid & 31;         // B float4 col in 128-n

    float4 pa[4], pb[4];
    const int nchunks = K >> 5;

    // prefetch + store chunk 0 into buffer 0
#pragma unroll
    for (int j = 0; j < 4; ++j) {
        pa[j] = *(const float4*)(Ab + (size_t)(am + 32 * j) * K + ac4 * 4);
        pb[j] = *(const float4*)(Bb + (size_t)(bk + 8 * j) * N + bn4 * 4);
    }
#pragma unroll
    for (int j = 0; j < 4; ++j)
        split_store8(smem + SM_AH, smem + SM_AL, pa[j],
                     (uint32_t)(am + 32 * j) * 80 + (uint32_t)ac4 * 8);
#pragma unroll
    for (int j = 0; j < 4; ++j)
        split_store8(smem + SM_BH, smem + SM_BL, pb[j],
                     (uint32_t)(bk + 8 * j) * 272 + (uint32_t)bn4 * 8);
    __syncthreads();

    for (int c = 0; c < nchunks; ++c) {
        const uint32_t bufr = (uint32_t)(c & 1) * GB;
        const uint32_t bufw = (uint32_t)((c + 1) & 1) * GB;
        const bool more = (c + 1 < nchunks);

        if (more) {
            const int kc = (c + 1) << 5;
#pragma unroll
            for (int j = 0; j < 4; ++j) {
                pa[j] = *(const float4*)(Ab + (size_t)(am + 32 * j) * K + kc + ac4 * 4);
                pb[j] = *(const float4*)(Bb + (size_t)(bk + kc + 8 * j) * N + bn4 * 4);
            }
        }

#pragma unroll
        for (int ks = 0; ks < 2; ++ks) {
            uint32_t ah[2][4], al[2][4];
#pragma unroll
            for (int mt = 0; mt < 2; ++mt) {
                uint32_t addr = aAddrBase + bufr + (uint32_t)(mt * 16) * 80 + (uint32_t)ks * 32;
                ldsm_x4(ah[mt], addr);
                ldsm_x4(al[mt], addr + (SM_AL - SM_AH));
            }
            uint32_t bh[4][4], bl[4][4];
#pragma unroll
            for (int ng = 0; ng < 4; ++ng) {
                uint32_t addr = bAddrBase + bufr + (uint32_t)(ks * 16) * 272 + (uint32_t)ng * 32;
                ldsm_x4_t(bh[ng], addr);
                ldsm_x4_t(bl[ng], addr + (SM_BL - SM_BH));
            }
#pragma unroll
            for (int mt = 0; mt < 2; ++mt) {
#pragma unroll
                for (int ng = 0; ng < 4; ++ng) {
                    mma2(acc[mt][2 * ng],     ah[mt], bh[ng][0], bh[ng][1]);
                    mma2(acc[mt][2 * ng],     ah[mt], bl[ng][0], bl[ng][1]);
                    mma2(acc[mt][2 * ng],     al[mt], bh[ng][0], bh[ng][1]);
                    mma2(acc[mt][2 * ng + 1], ah[mt], bh[ng][2], bh[ng][3]);
                    mma2(acc[mt][2 * ng + 1], ah[mt], bl[ng][2], bl[ng][3]);
                    mma2(acc[mt][2 * ng + 1], al[mt], bh[ng][2], bh[ng][3]);
                }
            }
            // interleave next-chunk STS between the two k-steps / after last
            if (more) {
                if (ks == 0) {
#pragma unroll
                    for (int j = 0; j < 4; ++j)
                        split_store8(smem + SM_AH + bufw, smem + SM_AL + bufw, pa[j],
                                     (uint32_t)(am + 32 * j) * 80 + (uint32_t)ac4 * 8);
                } else {
#pragma unroll
                    for (int j = 0; j < 4; ++j)
                        split_store8(smem + SM_BH + bufw, smem + SM_BL + bufw, pb[j],
                                     (uint32_t)(bk + 8 * j) * 272 + (uint32_t)bn4 * 8);
                }
            }
        }
        __syncthreads();
    }

    // ---- epilogue ----
    const int row0 = by * 128 + warp_m * 32 + (lane >> 2);
    const int col0 = bx * 128 + warp_n * 64 + (lane & 3) * 2;
#pragma unroll
    for (int mt = 0; mt < 2; ++mt) {
#pragma unroll
        for (int nt = 0; nt < 8; ++nt) {
            int r = row0 + mt * 16;
            int ccol = col0 + nt * 8;
            float b0 = bias[ccol], b1 = bias[ccol + 1];
            float2 v0 = make_float2(acc[mt][nt][0] + b0, acc[mt][nt][1] + b1);
            float2 v1 = make_float2(acc[mt][nt][2] + b0, acc[mt][nt][3] + b1);
            *(float2*)(C + (size_t)r * N + ccol) = v0;
            *(float2*)(C + (size_t)(r + 8) * N + ccol) = v1;
        }
    }
}

// ============================================================================
// MMA local attention.
// Block = (q-tile 64, head, batch), 128 threads (4 warps). Warp w owns S rows
// [16w,16w+16) x all <=192 keys. Q/K/V in smem as bf16 hi/lo (Dekker split),
// row stride 144B (72 bf16) -> conflict-free ldmatrix.
// S via mma(Q,K^T) 3-pass split; softmax on fragments; PV via mma(P,V) 3-pass
// split with P repacked in-register (S C-frag == PV A-frag layout).
// nrows is always 128 (edge) or 192 (interior); tail tiles skipped.
// ============================================================================
#define AT_STR 144
#define AQ_H 0
#define AQ_L (AQ_H + 64 * AT_STR)
#define AK_H (AQ_L + 64 * AT_STR)
#define AK_L (AK_H + 192 * AT_STR)
#define AV_H (AK_L + 192 * AT_STR)
#define AV_L (AV_H + 192 * AT_STR)
#define ATTN_SMEM (AV_L + 192 * AT_STR)    // 129024 B

__global__ __launch_bounds__(128, 1)
void attn_mma_kernel()
{
    extern __shared__ char smem[];
    const uint32_t sb = smem_to_u32(smem);
    const int tid = threadIdx.x;
    const int lane = tid & 31, w = tid >> 5;
    const int qt = blockIdx.x, h = blockIdx.y, b = blockIdx.z;
    const int i0 = qt * 64;
    const int jstart = max(0, i0 - HALFW);
    const int jend   = min(NTOK, i0 + 64 + HALFW);
    const int nrows  = jend - jstart;          // 128 or 192

    const float* qkv = g_qkv;

    // ---- load + split Q (64 rows x 64 d) ----
#pragma unroll
    for (int jj = 0; jj < 8; ++jj) {
        int idx = tid + jj * 128;
        int r = idx >> 4, dg = idx & 15;
        float4 v = *(const float4*)(qkv + (size_t)(b * NTOK + i0 + r) * (3 * DMODEL)
                                    + h * DHEAD + dg * 4);
        split_store8(smem + AQ_H, smem + AQ_L, v, (uint32_t)r * AT_STR + dg * 8);
    }
    // ---- load + split K/V (nrows x 64 d each) ----
#pragma unroll
    for (int jj = 0; jj < 24; ++jj) {
        int idx = tid + jj * 128;
        int r = idx >> 4, dg = idx & 15;
        if (r < nrows) {
            size_t base = (size_t)(b * NTOK + jstart + r) * (3 * DMODEL) + h * DHEAD + dg * 4;
            float4 kv = *(const float4*)(qkv + base + DMODEL);
            float4 vv = *(const float4*)(qkv + base + 2 * DMODEL);
            uint32_t off = (uint32_t)r * AT_STR + dg * 8;
            split_store8(smem + AK_H, smem + AK_L, kv, off);
            split_store8(smem + AV_H, smem + AV_L, vv, off);
        }
    }
    __syncthreads();

    // ---- Q fragments (all 4 k-steps, hi+lo) ----
    uint32_t qh[4][4], ql[4][4];
    const uint32_t qaddr = sb + AQ_H + (uint32_t)(w * 16 + (lane & 15)) * AT_STR
                         + (uint32_t)(lane >> 4) * 16;
#pragma unroll
    for (int ks = 0; ks < 4; ++ks) {
        ldsm_x4(qh[ks], qaddr + ks * 32);
        ldsm_x4(ql[ks], qaddr + ks * 32 + (AQ_L - AQ_H));
    }

    // ---- S = Q K^T ----
    float sacc[24][4];
#pragma unroll
    for (int nt = 0; nt < 24; ++nt)
#pragma unroll
        for (int e = 0; e < 4; ++e) sacc[nt][e] = 0.0f;

    const uint32_t kaddr0 = sb + AK_H + (uint32_t)(lane & 15) * AT_STR
                          + (uint32_t)(lane >> 4) * 16;
#pragma unroll
    for (int jt = 0; jt < 12; ++jt) {
        if (jt * 16 < nrows) {
#pragma unroll
            for (int ks = 0; ks < 4; ++ks) {
                uint32_t kh[4], kl[4];
                uint32_t ad = kaddr0 + (uint32_t)(jt * 16) * AT_STR + (uint32_t)ks * 32;
                ldsm_x4(kh, ad);
                ldsm_x4(kl, ad + (AK_L - AK_H));
                // non-trans pairing: frag(j-tile even) = {r0,r2}, odd = {r1,r3}
                mma2(sacc[2 * jt],     qh[ks], kh[0], kh[2]);
                mma2(sacc[2 * jt],     qh[ks], kl[0], kl[2]);
                mma2(sacc[2 * jt],     ql[ks], kh[0], kh[2]);
                mma2(sacc[2 * jt + 1], qh[ks], kh[1], kh[3]);
                mma2(sacc[2 * jt + 1], qh[ks], kl[1], kl[3]);
                mma2(sacc[2 * jt + 1], ql[ks], kh[1], kh[3]);
            }
        }
    }

    // ---- mask + scale + softmax (rows irow0, irow1 per thread) ----
    const int irow0 = i0 + w * 16 + (lane >> 2);
    const int irow1 = irow0 + 8;
    const int lo0 = irow0 - HALFW, hi0 = irow0 + HALFW;
    const int lo1 = irow1 - HALFW, hi1 = irow1 + HALFW;

    float mx0 = -1e30f, mx1 = -1e30f;
#pragma unroll
    for (int nt = 0; nt < 24; ++nt) {
        int j0 = jstart + nt * 8 + (lane & 3) * 2;
        int j1 = j0 + 1;
        sacc[nt][0] = (j0 < jend && j0 >= lo0 && j0 <= hi0) ? sacc[nt][0] * 0.125f : -1e30f;
        sacc[nt][1] = (j1 < jend && j1 >= lo0 && j1 <= hi0) ? sacc[nt][1] * 0.125f : -1e30f;
        sacc[nt][2] = (j0 < jend && j0 >= lo1 && j0 <= hi1) ? sacc[nt][2] * 0.125f : -1e30f;
        sacc[nt][3] = (j1 < jend && j1 >= lo1 && j1 <= hi1) ? sacc[nt][3] * 0.125f : -1e30f;
        mx0 = fmaxf(mx0, fmaxf(sacc[nt][0], sacc[nt][1]));
        mx1 = fmaxf(mx1, fmaxf(sacc[nt][2], sacc[nt][3]));
    }
    mx0 = fmaxf(mx0, __shfl_xor_sync(0xffffffffu, mx0, 1));
    mx0 = fmaxf(mx0, __shfl_xor_sync(0xffffffffu, mx0, 2));
    mx1 = fmaxf(mx1, __shfl_xor_sync(0xffffffffu, mx1, 1));
    mx1 = fmaxf(mx1, __shfl_xor_sync(0xffffffffu, mx1, 2));

    float sum0 = 0.0f, sum1 = 0.0f;
#pragma unroll
    for (int nt = 0; nt < 24; ++nt) {
        float e0 = __expf(sacc[nt][0] - mx0);
        float e1 = __expf(sacc[nt][1] - mx0);
        float e2 = __expf(sacc[nt][2] - mx1);
        float e3 = __expf(sacc[nt][3] - mx1);
        sacc[nt][0] = e0; sacc[nt][1] = e1; sacc[nt][2] = e2; sacc[nt][3] = e3;
        sum0 += e0 + e1;
        sum1 += e2 + e3;
    }
    sum0 += __shfl_xor_sync(0xffffffffu, sum0, 1);
    sum0 += __shfl_xor_sync(0xffffffffu, sum0, 2);
    sum1 += __shfl_xor_sync(0xffffffffu, sum1, 1);
    sum1 += __shfl_xor_sync(0xffffffffu, sum1, 2);
    const float inv0 = 1.0f / sum0;
    const float inv1 = 1.0f / sum1;

    // ---- O = P V ----
    float out[8][4];
#pragma unroll
    for (int dt = 0; dt < 8; ++dt)
#pragma unroll
        for (int e = 0; e < 4; ++e) out[dt][e] = 0.0f;

    const uint32_t vaddr0 = sb + AV_H + (uint32_t)(lane & 15) * AT_STR
                          + (uint32_t)(lane >> 4) * 16;
#pragma unroll
    for (int kt = 0; kt < 12; ++kt) {
        if (kt * 16 < nrows) {
            // P A-fragments from S C-fragments (hi + Dekker lo)
            const float* t0 = sacc[2 * kt];
            const float* t1 = sacc[2 * kt + 1];
            uint32_t pah[4], pal[4];
            pah[0] = cvt2_bf16(t0[0], t0[1]);
            pah[1] = cvt2_bf16(t0[2], t0[3]);
            pah[2] = cvt2_bf16(t1[0], t1[1]);
            pah[3] = cvt2_bf16(t1[2], t1[3]);
            float r00 = t0[0] - __uint_as_float(pah[0] << 16);
            float r01 = t0[1] - __uint_as_float(pah[0] & 0xFFFF0000u);
            float r02 = t0[2] - __uint_as_float(pah[1] << 16);
            float r03 = t0[3] - __uint_as_float(pah[1] & 0xFFFF0000u);
            float r10 = t1[0] - __uint_as_float(pah[2] << 16);
            float r11 = t1[1] - __uint_as_float(pah[2] & 0xFFFF0000u);
            float r12 = t1[2] - __uint_as_float(pah[3] << 16);
            float r13 = t1[3] - __uint_as_float(pah[3] & 0xFFFF0000u);
            pal[0] = cvt2_bf16(r00, r01);
            pal[1] = cvt2_bf16(r02, r03);
            pal[2] = cvt2_bf16(r10, r11);
            pal[3] = cvt2_bf16(r12, r13);

#pragma unroll
            for (int dp = 0; dp < 4; ++dp) {
                uint32_t vh[4], vl[4];
                uint32_t ad = vaddr0 + (uint32_t)(kt * 16) * AT_STR + (uint32_t)dp * 32;
                ldsm_x4_t(vh, ad);
                ldsm_x4_t(vl, ad + (AV_L - AV_H));
                // trans pairing: frag(d-tile 2dp) = {r0,r1}, 2dp+1 = {r2,r3}
                mma2(out[2 * dp],     pah, vh[0], vh[1]);
                mma2(out[2 * dp],     pah, vl[0], vl[1]);
                mma2(out[2 * dp],     pal, vh[0], vh[1]);
                mma2(out[2 * dp + 1], pah, vh[2], vh[3]);
                mma2(out[2 * dp + 1], pah, vl[2], vl[3]);
                mma2(out[2 * dp + 1], pal, vh[2], vh[3]);
            }
        }
    }

    // ---- epilogue: normalize + store ----
#pragma unroll
    for (int dt = 0; dt < 8; ++dt) {
        int d = dt * 8 + (lane & 3) * 2;
        float2 o0 = make_float2(out[dt][0] * inv0, out[dt][1] * inv0);
        float2 o1 = make_float2(out[dt][2] * inv1, out[dt][3] * inv1);
        *(float2*)(g_att + (size_t)(b * NTOK + irow0) * DMODEL + h * DHEAD + d) = o0;
        *(float2*)(g_att + (size_t)(b * NTOK + irow1) * DMODEL + h * DHEAD + d) = o1;
    }
}

// ---------------------------------------------------------------------------
extern "C" void kernel_launch(void* const* d_in, const int* in_sizes, int n_in,
                              void* d_out, int out_size)
{
    const float* x     = (const float*)d_in[0];
    const float* Wqkv  = (const float*)d_in[1];
    const float* bqkv  = (const float*)d_in[2];
    const float* Wout  = (const float*)d_in[3];
    const float* bout  = (const float*)d_in[4];
    float* out = (float*)d_out;

    float *qkv_ptr, *att_ptr;
    cudaGetSymbolAddress((void**)&qkv_ptr, g_qkv);
    cudaGetSymbolAddress((void**)&att_ptr, g_att);

    cudaFuncSetAttribute(tc_gemm_bias, cudaFuncAttributeMaxDynamicSharedMemorySize,
                         GEMM_SMEM_TOTAL);
    cudaFuncSetAttribute(attn_mma_kernel, cudaFuncAttributeMaxDynamicSharedMemorySize,
                         ATTN_SMEM);

    const int M = BATCH * NTOK;        // 4096

    // GEMM1: qkv = x @ Wqkv + bqkv   [4096 x 3072]
    dim3 g1(3 * DMODEL / 128, M / 128);
    tc_gemm_bias<<<g1, 256, GEMM_SMEM_TOTAL>>>(x, Wqkv, bqkv, qkv_ptr,
                                               M, 3 * DMODEL, DMODEL);

    // Local attention -> g_att
    dim3 ga(NTOK / 64, NHEAD, BATCH);
    attn_mma_kernel<<<ga, 128, ATTN_SMEM>>>();

    // GEMM2: out = att @ Wout + bout  [4096 x 1024]
    dim3 g2(DMODEL / 128, M / 128);
    tc_gemm_bias<<<g2, 256, GEMM_SMEM_TOTAL>>>(att_ptr, Wout, bout, out,
                                               M, DMODEL, DMODEL);
}